// round 16
// baseline (speedup 1.0000x reference)
#include <cuda_runtime.h>
#include <cuda_fp16.h>
#include <cstdint>

#define N_PIX 4096
#define BATCH 4
#define CDIM  64
#define CQKD  8
#define TQ    128                 // queries per block (8 warps x 16)
#define TK    64                  // keys per tile
#define NTILE (N_PIX / TK)        // 64
#define NSPLIT 4
#define TPS   (NTILE / NSPLIT)    // 16 tiles per split
#define LOG2E 1.4426950408889634f
#define BSHIFT 8.0f               // bound slack shift: p <= 2^8, avoids fp16 subnormals

#define KSTR  20   // k_sm row stride in words (hi interleaved d at +0, lo at +8, pad 4)
#define VSTR  72   // v_sm row stride in halfs (64 keys + 8 pad)

// Scratch (device globals: no allocation allowed)
// g_k is stored with INTERLEAVED d-order [d0,d4,d1,d5,d2,d6,d3,d7]
// g_vh is stored with keys PERMUTED within each 16-pixel group:
//   slot(j) = ((j&6)<<1) | (j&1) | ((j&8)>>2)
__device__ float  g_q[BATCH * N_PIX * CQKD];    // [b][pix][d], scaled by LOG2E
__device__ float  g_k[BATCH * N_PIX * CQKD];    // [b][pix][d-interleaved]
__device__ __half g_vh[BATCH * CDIM * N_PIX];   // [b][c][pix-permuted], fp16
__device__ float  g_pacc[NSPLIT * BATCH * CDIM * N_PIX]; // [s][b][c][pix]
__device__ float  g_pl[NSPLIT * BATCH * N_PIX];
__device__ int    g_kmax2[BATCH];               // max ||k||^2 (float bits, >=0)

// ---------------- helpers ----------------
__device__ __forceinline__ uint32_t tf32r(float x) {
    uint32_t u;
    asm("cvt.rna.tf32.f32 %0, %1;" : "=r"(u) : "f"(x));
    return u;
}
__device__ __forceinline__ float ex2(float x) {
    float r;
    asm("ex2.approx.f32 %0, %1;" : "=f"(r) : "f"(x));
    return r;
}
__device__ __forceinline__ uint32_t h2pack(float hi, float lo) {
    uint32_t d;
    asm("cvt.rn.f16x2.f32 %0, %1, %2;" : "=r"(d) : "f"(hi), "f"(lo));
    return d;
}
__device__ __forceinline__ void mma_tf32(float* c, const uint32_t* a,
                                         uint32_t b0, uint32_t b1) {
    asm volatile(
        "mma.sync.aligned.m16n8k8.row.col.f32.tf32.tf32.f32 "
        "{%0,%1,%2,%3}, {%4,%5,%6,%7}, {%8,%9}, {%0,%1,%2,%3};"
        : "+f"(c[0]), "+f"(c[1]), "+f"(c[2]), "+f"(c[3])
        : "r"(a[0]), "r"(a[1]), "r"(a[2]), "r"(a[3]), "r"(b0), "r"(b1));
}
__device__ __forceinline__ void mma_f16(float* c, const uint32_t* a,
                                        uint32_t b0, uint32_t b1) {
    asm volatile(
        "mma.sync.aligned.m16n8k16.row.col.f32.f16.f16.f32 "
        "{%0,%1,%2,%3}, {%4,%5,%6,%7}, {%8,%9}, {%0,%1,%2,%3};"
        : "+f"(c[0]), "+f"(c[1]), "+f"(c[2]), "+f"(c[3])
        : "r"(a[0]), "r"(a[1]), "r"(a[2]), "r"(a[3]), "r"(b0), "r"(b1));
}

// ============================================================
// Kernel 0: reset kmax accumulators (graph-replay deterministic)
// ============================================================
__global__ void init_kernel() {
    if (threadIdx.x < BATCH) g_kmax2[threadIdx.x] = 0;
}

// ============================================================
// Kernel 1: fused QKV projection.
//   g_q: [pix][d] fp32 (x LOG2E);  g_k: [pix][d-interleaved] fp32;
//   g_vh: [c][pix-permuted] fp16;  g_kmax2[b] = max ||k||^2
// ============================================================
__global__ __launch_bounds__(256) void qkv_kernel(
    const float* __restrict__ x,
    const float* __restrict__ Wq, const float* __restrict__ bq,
    const float* __restrict__ Wk, const float* __restrict__ bk,
    const float* __restrict__ Wv, const float* __restrict__ bv)
{
    __shared__ float x_s[64 * 68];
    __shared__ float w_s[80 * 64];
    __shared__ float b_s[80];

    const int b  = blockIdx.y;
    const int i0 = blockIdx.x * 64;
    const int tid = threadIdx.x;

    for (int idx = tid; idx < 1280; idx += 256) {
        float4 w;
        if (idx < 128)      w = reinterpret_cast<const float4*>(Wq)[idx];
        else if (idx < 256) w = reinterpret_cast<const float4*>(Wk)[idx - 128];
        else                w = reinterpret_cast<const float4*>(Wv)[idx - 256];
        reinterpret_cast<float4*>(w_s)[idx] = w;
    }
    if (tid < 8)       b_s[tid] = bq[tid];
    else if (tid < 16) b_s[tid] = bk[tid - 8];
    else if (tid < 80) b_s[tid] = bv[tid - 16];

    for (int idx = tid; idx < 1024; idx += 256) {
        int c = idx >> 4, p4 = (idx & 15) * 4;
        float4 xv = *reinterpret_cast<const float4*>(
            &x[(b * CDIM + c) * N_PIX + i0 + p4]);
        *reinterpret_cast<float4*>(&x_s[c * 68 + p4]) = xv;
    }
    __syncthreads();

    const int og = tid >> 6;   // 0..3
    const int p  = tid & 63;

    float acc[20];
#pragma unroll
    for (int k = 0; k < 20; k++) acc[k] = b_s[og * 20 + k];

#pragma unroll 8
    for (int c = 0; c < 64; c++) {
        float xv = x_s[c * 68 + p];
#pragma unroll
        for (int k = 0; k < 20; k++)
            acc[k] += w_s[(og * 20 + k) * 64 + c] * xv;
    }

    const int pix = i0 + p;
    // key-slot permutation within 16-pixel group (for fp16 V b-frag LDS.64)
    const int j4 = p & 15;
    const int vslot = ((j4 & 6) << 1) | (j4 & 1) | ((j4 & 8) >> 2);
    const int vpix = i0 + (p & ~15) + vslot;

    if (og == 0) {
        float4 q0 = make_float4(acc[0] * LOG2E, acc[1] * LOG2E,
                                acc[2] * LOG2E, acc[3] * LOG2E);
        float4 q1 = make_float4(acc[4] * LOG2E, acc[5] * LOG2E,
                                acc[6] * LOG2E, acc[7] * LOG2E);
        *reinterpret_cast<float4*>(&g_q[(b * N_PIX + pix) * 8])     = q0;
        *reinterpret_cast<float4*>(&g_q[(b * N_PIX + pix) * 8 + 4]) = q1;
        // interleaved d-order: slots = d0,d4,d1,d5,d2,d6,d3,d7
        float4 k0 = make_float4(acc[8],  acc[12], acc[9],  acc[13]);
        float4 k1 = make_float4(acc[10], acc[14], acc[11], acc[15]);
        *reinterpret_cast<float4*>(&g_k[(b * N_PIX + pix) * 8])     = k0;
        *reinterpret_cast<float4*>(&g_k[(b * N_PIX + pix) * 8 + 4]) = k1;
#pragma unroll
        for (int k = 16; k < 20; k++)
            g_vh[(b * CDIM + (k - 16)) * N_PIX + vpix] = __float2half_rn(acc[k]);
        // ||k||^2 reduction -> atomicMax
        float kk = 0.f;
#pragma unroll
        for (int k = 8; k < 16; k++) kk += acc[k] * acc[k];
#pragma unroll
        for (int msk = 16; msk >= 1; msk >>= 1)
            kk = fmaxf(kk, __shfl_xor_sync(0xffffffffu, kk, msk));
        if ((tid & 31) == 0)
            atomicMax(&g_kmax2[b], __float_as_int(kk));
    } else {
#pragma unroll
        for (int k = 0; k < 20; k++) {
            int c = og * 20 + k - 16;
            g_vh[(b * CDIM + c) * N_PIX + vpix] = __float2half_rn(acc[k]);
        }
    }
}

// ============================================================
// Kernel 2: FlashAttention on mma.sync, SPLIT-KV x4, bound softmax
// (no online rescale), double-buffered smem with register prefetch.
// grid (32, 4, 4), 256 threads (8 warps).
// ============================================================
__global__ __launch_bounds__(256, 2) void attn_kernel()
{
    __shared__ __align__(16) float  k_sm[2][TK * KSTR];
    __shared__ __align__(16) __half v_sm[2][CDIM * VSTR];

    const int b    = blockIdx.y;
    const int s    = blockIdx.z;
    const int i0   = blockIdx.x * TQ;
    const int tid  = threadIdx.x;
    const int wid  = tid >> 5;
    const int lane = tid & 31;
    const int gid  = lane >> 2;
    const int tig  = lane & 3;
    const int qrow = wid * 16 + gid;

    const int kpix  = tid >> 2, kpart = tid & 3;
    const int vc0 = tid >> 3,         vm0 = tid & 7;
    const int vc1 = (tid + 256) >> 3, vm1 = (tid + 256) & 7;

    // ---- Q A-fragments (hi/lo tf32) + bounds ----
    uint32_t a_hi[4], a_lo[4];
    float bound0, bound1;
    {
        const float* qb = &g_q[(b * N_PIX + i0) * 8];
        float qv[4];
        qv[0] = qb[(qrow)     * 8 + tig];
        qv[1] = qb[(qrow + 8) * 8 + tig];
        qv[2] = qb[(qrow)     * 8 + tig + 4];
        qv[3] = qb[(qrow + 8) * 8 + tig + 4];
#pragma unroll
        for (int i = 0; i < 4; i++) {
            a_hi[i] = tf32r(qv[i]);
            a_lo[i] = tf32r(qv[i] - __uint_as_float(a_hi[i]));
        }
        float qn0 = qv[0] * qv[0] + qv[2] * qv[2];
        float qn1 = qv[1] * qv[1] + qv[3] * qv[3];
        qn0 += __shfl_xor_sync(0xffffffffu, qn0, 1);
        qn0 += __shfl_xor_sync(0xffffffffu, qn0, 2);
        qn1 += __shfl_xor_sync(0xffffffffu, qn1, 1);
        qn1 += __shfl_xor_sync(0xffffffffu, qn1, 2);
        const float kmax = sqrtf(__int_as_float(g_kmax2[b]));
        bound0 = sqrtf(qn0) * kmax - BSHIFT;   // >= max_j s (log2 domain) - 8
        bound1 = sqrtf(qn1) * kmax - BSHIFT;
    }

    float lp0 = 0.f, lp1 = 0.f;
    float o[8][4];
#pragma unroll
    for (int nt = 0; nt < 8; nt++)
#pragma unroll
        for (int e = 0; e < 4; e++) o[nt][e] = 0.f;

    const int t0 = s * TPS, t1 = t0 + TPS;

    // ---- prologue: fill buffer 0 with tile t0 ----
    {
        const int jg = t0 * TK;
        float2 pk = *reinterpret_cast<const float2*>(
            &g_k[(b * N_PIX + jg + kpix) * 8 + 2 * kpart]);
        uint4 pv0 = *reinterpret_cast<const uint4*>(
            &g_vh[(b * CDIM + vc0) * N_PIX + jg + vm0 * 8]);
        uint4 pv1 = *reinterpret_cast<const uint4*>(
            &g_vh[(b * CDIM + vc1) * N_PIX + jg + vm1 * 8]);
        uint32_t h0 = tf32r(pk.x), h1 = tf32r(pk.y);
        uint32_t lo0 = tf32r(pk.x - __uint_as_float(h0));
        uint32_t lo1 = tf32r(pk.y - __uint_as_float(h1));
        float* row = &k_sm[0][kpix * KSTR];
        *reinterpret_cast<float2*>(&row[2 * kpart]) =
            make_float2(__uint_as_float(h0), __uint_as_float(h1));
        *reinterpret_cast<float2*>(&row[8 + 2 * kpart]) =
            make_float2(__uint_as_float(lo0), __uint_as_float(lo1));
        *reinterpret_cast<uint4*>(&v_sm[0][vc0 * VSTR + vm0 * 8]) = pv0;
        *reinterpret_cast<uint4*>(&v_sm[0][vc1 * VSTR + vm1 * 8]) = pv1;
        __syncthreads();
    }

    for (int t = t0; t < t1; t++) {
        const int buf = (t - t0) & 1;
        const int tn = (t + 1 < t1) ? t + 1 : t;
        const int jn = tn * TK;
        float2 pk = *reinterpret_cast<const float2*>(
            &g_k[(b * N_PIX + jn + kpix) * 8 + 2 * kpart]);
        uint4 pv0 = *reinterpret_cast<const uint4*>(
            &g_vh[(b * CDIM + vc0) * N_PIX + jn + vm0 * 8]);
        uint4 pv1 = *reinterpret_cast<const uint4*>(
            &g_vh[(b * CDIM + vc1) * N_PIX + jn + vm1 * 8]);

        // ---- S = Q K^T (3xTF32), vectorized B-frag loads ----
        float sreg[8][4];
#pragma unroll
        for (int nt = 0; nt < 8; nt++)
#pragma unroll
            for (int e = 0; e < 4; e++) sreg[nt][e] = 0.f;

#pragma unroll
        for (int nt = 0; nt < 8; nt++) {
            const float* kr = &k_sm[buf][(8 * nt + gid) * KSTR];
            float2 bh = *reinterpret_cast<const float2*>(&kr[2 * tig]);
            float2 bl = *reinterpret_cast<const float2*>(&kr[8 + 2 * tig]);
            mma_tf32(sreg[nt], a_hi, __float_as_uint(bh.x), __float_as_uint(bh.y));
            mma_tf32(sreg[nt], a_hi, __float_as_uint(bl.x), __float_as_uint(bl.y));
            mma_tf32(sreg[nt], a_lo, __float_as_uint(bh.x), __float_as_uint(bh.y));
        }

        // ---- bound softmax: p = 2^(s - bound); accumulate l per-thread ----
        float p[8][4];
#pragma unroll
        for (int nt = 0; nt < 8; nt++) {
            p[nt][0] = ex2(sreg[nt][0] - bound0);
            p[nt][1] = ex2(sreg[nt][1] - bound0);
            p[nt][2] = ex2(sreg[nt][2] - bound1);
            p[nt][3] = ex2(sreg[nt][3] - bound1);
            lp0 += p[nt][0] + p[nt][1];
            lp1 += p[nt][2] + p[nt][3];
        }

        // ---- PV: fp16 mma, one LDS.64 per (kk,ntc) (permuted V slots) ----
#pragma unroll
        for (int kk = 0; kk < 4; kk++) {
            uint32_t af[4];
            af[0] = h2pack(p[2 * kk][1],     p[2 * kk][0]);
            af[1] = h2pack(p[2 * kk][3],     p[2 * kk][2]);
            af[2] = h2pack(p[2 * kk + 1][1], p[2 * kk + 1][0]);
            af[3] = h2pack(p[2 * kk + 1][3], p[2 * kk + 1][2]);
#pragma unroll
            for (int ntc = 0; ntc < 8; ntc++) {
                int cc = 8 * ntc + gid;
                uint2 bb = *reinterpret_cast<const uint2*>(
                    &v_sm[buf][cc * VSTR + 16 * kk + 4 * tig]);
                mma_f16(o[ntc], af, bb.x, bb.y);
            }
        }

        // ---- store prefetched tile into other buffer ----
        {
            uint32_t h0 = tf32r(pk.x), h1 = tf32r(pk.y);
            uint32_t lo0 = tf32r(pk.x - __uint_as_float(h0));
            uint32_t lo1 = tf32r(pk.y - __uint_as_float(h1));
            float* row = &k_sm[buf ^ 1][kpix * KSTR];
            *reinterpret_cast<float2*>(&row[2 * kpart]) =
                make_float2(__uint_as_float(h0), __uint_as_float(h1));
            *reinterpret_cast<float2*>(&row[8 + 2 * kpart]) =
                make_float2(__uint_as_float(lo0), __uint_as_float(lo1));
            *reinterpret_cast<uint4*>(&v_sm[buf ^ 1][vc0 * VSTR + vm0 * 8]) = pv0;
            *reinterpret_cast<uint4*>(&v_sm[buf ^ 1][vc1 * VSTR + vm1 * 8]) = pv1;
        }
        __syncthreads();
    }

    // ---- reduce l across tig lanes, write partials ----
    lp0 += __shfl_xor_sync(0xffffffffu, lp0, 1);
    lp0 += __shfl_xor_sync(0xffffffffu, lp0, 2);
    lp1 += __shfl_xor_sync(0xffffffffu, lp1, 1);
    lp1 += __shfl_xor_sync(0xffffffffu, lp1, 2);

#pragma unroll
    for (int ntc = 0; ntc < 8; ntc++) {
#pragma unroll
        for (int e = 0; e < 2; e++) {
            int c = 8 * ntc + 2 * tig + e;
            int a0 = ((s * BATCH + b) * CDIM + c) * N_PIX + i0 + qrow;
            g_pacc[a0]     = o[ntc][e];
            g_pacc[a0 + 8] = o[ntc][2 + e];
        }
    }
    if (tig == 0) {
        int qa = (s * BATCH + b) * N_PIX + i0 + qrow;
        g_pl[qa]     = lp0;
        g_pl[qa + 8] = lp1;
    }
}

// ============================================================
// Kernel 3: combine 4 splits + gamma*out + x residual
// (all splits share the same per-row bound -> out = sum(a)/sum(l))
// ============================================================
__global__ __launch_bounds__(256) void combine_kernel(
    const float* __restrict__ x,
    const float* __restrict__ gamma,
    float* __restrict__ out)
{
    const int idx  = blockIdx.x * 256 + threadIdx.x;
    const int pix4 = idx & 1023;
    const int c    = (idx >> 10) & 63;
    const int b    = idx >> 16;
    const int pix  = pix4 * 4;

    float4 lsum = make_float4(0.f, 0.f, 0.f, 0.f);
    float4 asum = make_float4(0.f, 0.f, 0.f, 0.f);
#pragma unroll
    for (int s = 0; s < NSPLIT; s++) {
        float4 lv = *reinterpret_cast<const float4*>(
            &g_pl[(s * BATCH + b) * N_PIX + pix]);
        lsum.x += lv.x; lsum.y += lv.y; lsum.z += lv.z; lsum.w += lv.w;
        float4 av = *reinterpret_cast<const float4*>(
            &g_pacc[((s * BATCH + b) * CDIM + c) * N_PIX + pix]);
        asum.x += av.x; asum.y += av.y; asum.z += av.z; asum.w += av.w;
    }

    const int gaddr = (b * CDIM + c) * N_PIX + pix;
    float4 xv = *reinterpret_cast<const float4*>(&x[gaddr]);
    const float g = gamma[0];

    float4 ov;
    ov.x = g * (asum.x / lsum.x) + xv.x;
    ov.y = g * (asum.y / lsum.y) + xv.y;
    ov.z = g * (asum.z / lsum.z) + xv.z;
    ov.w = g * (asum.w / lsum.w) + xv.w;
    *reinterpret_cast<float4*>(&out[gaddr]) = ov;
}

extern "C" void kernel_launch(void* const* d_in, const int* in_sizes, int n_in,
                              void* d_out, int out_size)
{
    const float* x     = (const float*)d_in[0];
    const float* Wq    = (const float*)d_in[1];
    const float* bq    = (const float*)d_in[2];
    const float* Wk    = (const float*)d_in[3];
    const float* bk    = (const float*)d_in[4];
    const float* Wv    = (const float*)d_in[5];
    const float* bv    = (const float*)d_in[6];
    const float* gamma = (const float*)d_in[7];
    float* out = (float*)d_out;

    init_kernel<<<1, 32>>>();
    qkv_kernel<<<dim3(64, BATCH), 256>>>(x, Wq, bq, Wk, bk, Wv, bv);
    attn_kernel<<<dim3(N_PIX / TQ, BATCH, NSPLIT), 256>>>();
    combine_kernel<<<(BATCH * CDIM * N_PIX / 4) / 256, 256>>>(x, gamma, out);
}